// round 11
// baseline (speedup 1.0000x reference)
#include <cuda_runtime.h>
#include <math.h>

typedef unsigned long long ull;

#define TT 2048
#define BB 64
#define II 128
#define HH 256
#define NBLK 128            /* 16 clusters x 8 CTAs */
#define CLUS 8
#define NTHR 1024
#define HXS  68             /* gx-kernel x staging row stride */
#define WST  132            /* W_h slice row stride (128 cols + 4 pad) */
#define HBS  6              /* hb row stride: 24B -> stride-6 banks, conflict-free */

// ---- device scratch (static) ----
__device__ __align__(16) float g_gx[(size_t)TT * BB * HH * 4];   // [t][b][j][g]

// ---- helpers ----
__device__ __forceinline__ ull pk2(float v) {
    ull r; unsigned u = __float_as_uint(v);
    asm("mov.b64 %0, {%1, %1};" : "=l"(r) : "r"(u));
    return r;
}
__device__ __forceinline__ void fma2(ull& d, ull a, ull b) {
    asm("fma.rn.f32x2 %0, %1, %2, %0;" : "+l"(d) : "l"(a), "l"(b));
}
__device__ __forceinline__ ull add2(ull a, ull b) {
    ull r; asm("add.rn.f32x2 %0, %1, %2;" : "=l"(r) : "l"(a), "l"(b));
    return r;
}
__device__ __forceinline__ float tanh_ap(float x) {
    float y; asm("tanh.approx.f32 %0, %1;" : "=f"(y) : "f"(x));
    return y;
}
__device__ __forceinline__ float sig_ap(float x) {
    return fmaf(0.5f, tanh_ap(0.5f * x), 0.5f);
}
__device__ __forceinline__ unsigned smem_u32(const void* p) {
    unsigned a;
    asm("{ .reg .u64 t; cvta.to.shared.u64 t, %1; cvt.u32.u64 %0, t; }"
        : "=r"(a) : "l"(p));
    return a;
}
__device__ __forceinline__ unsigned mapa_rank(unsigned laddr, unsigned rank) {
    unsigned r;
    asm("mapa.shared::cluster.u32 %0, %1, %2;" : "=r"(r) : "r"(laddr), "r"(rank));
    return r;
}
#define CLUSTER_ARRIVE() asm volatile("barrier.cluster.arrive.aligned;" ::: "memory")
#define CLUSTER_WAIT()   asm volatile("barrier.cluster.wait.aligned;" ::: "memory")

// ============================================================
// Kernel 1: precompute gx[t][b][j][g] = (x_t . W_x), transpose fused.
// grid (t=2048, cb=8): cb covers h-cols 32cb..32cb+31 (x 4 gates).
// ============================================================
#define GX_XS 0
#define GX_WS (II * HXS)
#define GX_SMEM_FLOATS (GX_WS + II * 128)
#define GX_SMEM_BYTES  (GX_SMEM_FLOATS * 4)

__global__ void __launch_bounds__(512) gx_kernel(const float* __restrict__ x,
                                                 const float* __restrict__ Wx)
{
    extern __shared__ float sm[];
    float* xs  = sm + GX_XS;    // xs[i*68 + b]
    float* ws2 = sm + GX_WS;    // ws2[k*128 + hl*4 + g]

    const int t    = blockIdx.x;
    const int cb   = blockIdx.y;
    const int tid  = threadIdx.x;
    const int lane = tid & 31;
    const int bq   = tid >> 5;

    #pragma unroll
    for (int jj = 0; jj < 16; ++jj) {
        int idx = tid + jj * 512;
        int b = idx >> 7, i = idx & 127;
        xs[i * HXS + b] = __ldg(x + ((size_t)b * TT + t) * II + i);
    }
    #pragma unroll
    for (int jj = 0; jj < 32; ++jj) {
        int idx = tid + jj * 512;
        int k = idx >> 7, rem = idx & 127;
        int g = rem >> 5, hl = rem & 31;
        ws2[k * 128 + hl * 4 + g] = __ldg(Wx + ((size_t)g * II + k) * HH + (cb << 5) + hl);
    }
    __syncthreads();

    ull acc2[8];
    #pragma unroll
    for (int i = 0; i < 8; ++i) acc2[i] = 0ull;

    const float* xp = xs + (bq << 2);
    const float* wp = ws2 + (lane << 2);
    #pragma unroll 4
    for (int k = 0; k < II; ++k) {
        float4 hv = *(const float4*)(xp + k * HXS);
        ulonglong2 wv = *(const ulonglong2*)(wp + k * 128);
        ull h0 = pk2(hv.x), h1 = pk2(hv.y), h2 = pk2(hv.z), h3 = pk2(hv.w);
        fma2(acc2[0], h0, wv.x); fma2(acc2[1], h0, wv.y);
        fma2(acc2[2], h1, wv.x); fma2(acc2[3], h1, wv.y);
        fma2(acc2[4], h2, wv.x); fma2(acc2[5], h2, wv.y);
        fma2(acc2[6], h3, wv.x); fma2(acc2[7], h3, wv.y);
    }

    #pragma unroll
    for (int r = 0; r < 4; ++r) {
        int b = (bq << 2) + r;
        ulonglong2 v; v.x = acc2[r * 2]; v.y = acc2[r * 2 + 1];
        *(ulonglong2*)(g_gx + (((size_t)t * BB + b) * HH + (cb << 5) + lane) * 4) = v;
    }
}

// ============================================================
// Kernel 2: clustered LSTM, 1024 threads, 16-reg accumulators.
// 16 clusters x 8 CTAs; cluster cid owns batches 4cid..4cid+3.
// CTA rank r owns j in [32r, 32r+32) (local col = jl*4 + g).
// Warp w: col-group wl = w&15 (cols 8wl..8wl+7), batch-pair bh = w>>4
//   (batches 2bh, 2bh+1). Lane: k-slice {lane+32u, u<8}.
// acc2[r*4+p] = (batch r, col-pair p) -> 16 scalars/lane.
// Butterfly n=8..2 + xor1 unpack + xor16 combine -> lane l<16 holds
// output (b=(l>>3)&1, col=l&7); lanes 16-31 are duplicates.
// SMEM: ws[256][132] @0, hb[2][256][6] @33792 (24B rows, stride-6 banks).
// ============================================================
#define SM_HB (HH * WST)                    /* 33792 floats */
#define SMEM_FLOATS (SM_HB + 2 * HH * HBS)  /* +3072 */
#define SMEM_BYTES  (SMEM_FLOATS * 4)

__global__ void __launch_bounds__(NTHR, 1) __cluster_dims__(CLUS, 1, 1)
lstm_kernel(const float* __restrict__ Wh, const float* __restrict__ bias,
            float* __restrict__ out)
{
    extern __shared__ float sm[];
    float* ws = sm;
    float* hb = sm + SM_HB;

    const int tid  = threadIdx.x;
    const int w    = tid >> 5;
    const int lane = tid & 31;
    const int wl   = w & 15;
    const int bh   = w >> 4;
    unsigned rank;
    asm("mov.u32 %0, %%cluster_ctarank;" : "=r"(rank));
    const int cid = blockIdx.x >> 3;

    // one-time: W_h slice ws[k*132 + jl*4 + g] = Wh[g][k][32r + jl]
    for (int idx = tid; idx < HH * 128; idx += NTHR) {
        int k = idx >> 7, rem = idx & 127;
        int g = rem >> 5, jl = rem & 31;
        ws[k * WST + jl * 4 + g] =
            __ldg(Wh + ((size_t)g * HH + k) * HH + (rank << 5) + jl);
    }

    const int  col  = (wl << 3) + (lane & 7);
    const int  b_l  = (lane >> 3) & 1;             // batch within pair
    const int  j    = (int)(rank << 5) + (col >> 2);
    const int  gg_  = col & 3;
    const int  bse  = lane & 28;
    const bool upd  = (lane & 19) == 0;            // lane<16 && (lane&3)==0
    const float biasv = __ldg(bias + (size_t)gg_ * HH + j);
    const int  myb  = (cid << 2) + (bh << 1) + b_l;
    const float* gxp = g_gx + (((size_t)myb * HH + j) << 2) + gg_;

    // hoisted: 8 remote hb base addresses (loop-invariant)
    const unsigned hb_u = smem_u32(hb);
    unsigned rb[CLUS];
    #pragma unroll
    for (int r = 0; r < CLUS; ++r) rb[r] = mapa_rank(hb_u, (unsigned)r);
    const unsigned joff = (unsigned)j * (HBS * 4) + ((unsigned)((bh << 1) + b_l) << 2);

    float creg = 0.f;
    __syncthreads();   // ws ready

    for (int t = 0; t < TT; ++t) {
        float gxv = __ldg(gxp + (size_t)t * (BB * HH * 4));  // issued before wait

        ull acc2[8];
        #pragma unroll
        for (int i = 0; i < 8; ++i) acc2[i] = 0ull;

        if (t > 0) {
            CLUSTER_WAIT();   // acquire: h_{t-1} visible in hb[t&1]
            const float* hbr = hb + (t & 1) * (HH * HBS) + (bh << 1);
            const float* wsw = ws + (wl << 3);
            #pragma unroll
            for (int u = 0; u < 8; ++u) {
                const int k = lane + (u << 5);
                float2 hv = *(const float2*)(hbr + k * HBS);
                ulonglong2 w0 = *(const ulonglong2*)(wsw + k * WST);
                ulonglong2 w1 = *(const ulonglong2*)(wsw + k * WST + 4);
                ull h0 = pk2(hv.x), h1 = pk2(hv.y);
                fma2(acc2[0], h0, w0.x); fma2(acc2[1], h0, w0.y);
                fma2(acc2[2], h0, w1.x); fma2(acc2[3], h0, w1.y);
                fma2(acc2[4], h1, w0.x); fma2(acc2[5], h1, w0.y);
                fma2(acc2[6], h1, w1.x); fma2(acc2[7], h1, w1.y);
            }
        }

        // packed butterfly reduce-scatter over lane bits 3..1
        #pragma unroll
        for (int n = 8; n >= 2; n >>= 1) {
            const int m = n >> 1;
            #pragma unroll
            for (int s = 0; s < m; ++s) {
                ull lo = acc2[s], hi = acc2[s + m];
                ull send = (lane & n) ? lo : hi;
                ull keep = (lane & n) ? hi : lo;
                acc2[s] = add2(keep, __shfl_xor_sync(0xffffffffu, send, n));
            }
        }
        // unpack + lane bit 0
        float pre;
        {
            unsigned u0, u1;
            asm("mov.b64 {%0, %1}, %2;" : "=r"(u0), "=r"(u1) : "l"(acc2[0]));
            float a0 = __uint_as_float(u0), a1 = __uint_as_float(u1);
            float send = (lane & 1) ? a0 : a1;
            float keep = (lane & 1) ? a1 : a0;
            pre = keep + __shfl_xor_sync(0xffffffffu, send, 1);
        }
        // combine lane-halves (lanes l and l^16 hold complementary k-partials)
        pre += __shfl_xor_sync(0xffffffffu, pre, 16);
        pre += gxv + biasv;

        // gather 4 gates (cols jl*4+0..3 live at lanes bse..bse+3)
        float pf = __shfl_sync(0xffffffffu, pre, bse | 1);
        float pg = __shfl_sync(0xffffffffu, pre, bse | 2);
        float po = __shfl_sync(0xffffffffu, pre, bse | 3);
        float hv_out = 0.f;
        if (upd) {
            float ig = sig_ap(pre);
            float fg = sig_ap(pf);
            float gv = tanh_ap(pg);
            float og = sig_ap(po);
            creg = fg * creg + ig * gv;
            hv_out = og * tanh_ap(creg);
            if (t + 1 < TT) {
                unsigned off = (unsigned)((t & 1) ^ 1) * (HH * HBS * 4) + joff;
                #pragma unroll
                for (int r = 0; r < CLUS; ++r) {
                    asm volatile("st.shared::cluster.f32 [%0], %1;"
                                 :: "r"(rb[r] + off), "f"(hv_out) : "memory");
                }
            }
        }

        CLUSTER_ARRIVE();   // release: h_t visible to peers after their wait

        if (upd)            // off the inter-CTA critical path
            out[((size_t)myb * TT + t) * HH + j] = hv_out;
    }
    CLUSTER_WAIT();         // matches final arrive; no early exit
}

// ============================================================
extern "C" void kernel_launch(void* const* d_in, const int* in_sizes, int n_in,
                              void* d_out, int out_size)
{
    const float* x  = (const float*)d_in[0];   // [B, T, I]
    const float* Wx = (const float*)d_in[1];   // [4, I, H]
    const float* Wh = (const float*)d_in[2];   // [4, H, H]
    const float* b  = (const float*)d_in[3];   // [4, H]
    float* out = (float*)d_out;                // [B, T, H]

    cudaFuncSetAttribute(gx_kernel,
                         cudaFuncAttributeMaxDynamicSharedMemorySize, GX_SMEM_BYTES);
    cudaFuncSetAttribute(lstm_kernel,
                         cudaFuncAttributeMaxDynamicSharedMemorySize, SMEM_BYTES);

    gx_kernel<<<dim3(TT, 8), 512, GX_SMEM_BYTES>>>(x, Wx);
    lstm_kernel<<<NBLK, NTHR, SMEM_BYTES>>>(Wh, b, out);
}

// round 12
// speedup vs baseline: 1.4010x; 1.4010x over previous
#include <cuda_runtime.h>
#include <math.h>

typedef unsigned long long ull;

#define TT 2048
#define BB 64
#define II 128
#define HH 256
#define NBLK 128            /* 16 clusters x 8 CTAs */
#define CLUS 8
#define NTHR 512
#define HXS  68             /* gx-kernel x staging row stride */
#define WST  132            /* W_h slice row stride (128 cols + 4 pad) */

// ---- device scratch (static) ----
__device__ __align__(16) float g_gx[(size_t)TT * BB * HH * 4];   // [t][b][j][g]

// ---- helpers ----
__device__ __forceinline__ ull pk2(float v) {
    ull r; unsigned u = __float_as_uint(v);
    asm("mov.b64 %0, {%1, %1};" : "=l"(r) : "r"(u));
    return r;
}
__device__ __forceinline__ void fma2(ull& d, ull a, ull b) {
    asm("fma.rn.f32x2 %0, %1, %2, %0;" : "+l"(d) : "l"(a), "l"(b));
}
__device__ __forceinline__ ull add2(ull a, ull b) {
    ull r; asm("add.rn.f32x2 %0, %1, %2;" : "=l"(r) : "l"(a), "l"(b));
    return r;
}
__device__ __forceinline__ float tanh_ap(float x) {
    float y; asm("tanh.approx.f32 %0, %1;" : "=f"(y) : "f"(x));
    return y;
}
__device__ __forceinline__ float sig_ap(float x) {
    return fmaf(0.5f, tanh_ap(0.5f * x), 0.5f);
}
__device__ __forceinline__ unsigned smem_u32(const void* p) {
    unsigned a;
    asm("{ .reg .u64 t; cvta.to.shared.u64 t, %1; cvt.u32.u64 %0, t; }"
        : "=r"(a) : "l"(p));
    return a;
}
__device__ __forceinline__ unsigned mapa_rank(unsigned laddr, unsigned rank) {
    unsigned r;
    asm("mapa.shared::cluster.u32 %0, %1, %2;" : "=r"(r) : "r"(laddr), "r"(rank));
    return r;
}
#define CLUSTER_ARRIVE() asm volatile("barrier.cluster.arrive.aligned;" ::: "memory")
#define CLUSTER_WAIT()   asm volatile("barrier.cluster.wait.aligned;" ::: "memory")

// ============================================================
// Kernel 1: precompute gx[t][b][j][g] = (x_t . W_x), transpose fused.
// grid (t=2048, cb=8): cb covers h-cols 32cb..32cb+31 (x 4 gates).
// ============================================================
#define GX_XS 0
#define GX_WS (II * HXS)
#define GX_SMEM_FLOATS (GX_WS + II * 128)
#define GX_SMEM_BYTES  (GX_SMEM_FLOATS * 4)

__global__ void __launch_bounds__(512) gx_kernel(const float* __restrict__ x,
                                                 const float* __restrict__ Wx)
{
    extern __shared__ float sm[];
    float* xs  = sm + GX_XS;    // xs[i*68 + b]
    float* ws2 = sm + GX_WS;    // ws2[k*128 + hl*4 + g]

    const int t    = blockIdx.x;
    const int cb   = blockIdx.y;
    const int tid  = threadIdx.x;
    const int lane = tid & 31;
    const int bq   = tid >> 5;

    #pragma unroll
    for (int jj = 0; jj < 16; ++jj) {
        int idx = tid + jj * 512;
        int b = idx >> 7, i = idx & 127;
        xs[i * HXS + b] = __ldg(x + ((size_t)b * TT + t) * II + i);
    }
    #pragma unroll
    for (int jj = 0; jj < 32; ++jj) {
        int idx = tid + jj * 512;
        int k = idx >> 7, rem = idx & 127;
        int g = rem >> 5, hl = rem & 31;
        ws2[k * 128 + hl * 4 + g] = __ldg(Wx + ((size_t)g * II + k) * HH + (cb << 5) + hl);
    }
    __syncthreads();

    ull acc2[8];
    #pragma unroll
    for (int i = 0; i < 8; ++i) acc2[i] = 0ull;

    const float* xp = xs + (bq << 2);
    const float* wp = ws2 + (lane << 2);
    #pragma unroll 4
    for (int k = 0; k < II; ++k) {
        float4 hv = *(const float4*)(xp + k * HXS);
        ulonglong2 wv = *(const ulonglong2*)(wp + k * 128);
        ull h0 = pk2(hv.x), h1 = pk2(hv.y), h2 = pk2(hv.z), h3 = pk2(hv.w);
        fma2(acc2[0], h0, wv.x); fma2(acc2[1], h0, wv.y);
        fma2(acc2[2], h1, wv.x); fma2(acc2[3], h1, wv.y);
        fma2(acc2[4], h2, wv.x); fma2(acc2[5], h2, wv.y);
        fma2(acc2[6], h3, wv.x); fma2(acc2[7], h3, wv.y);
    }

    #pragma unroll
    for (int r = 0; r < 4; ++r) {
        int b = (bq << 2) + r;
        ulonglong2 v; v.x = acc2[r * 2]; v.y = acc2[r * 2 + 1];
        *(ulonglong2*)(g_gx + (((size_t)t * BB + b) * HH + (cb << 5) + lane) * 4) = v;
    }
}

// ============================================================
// Kernel 2: clustered LSTM (R10 structure), st.async h-exchange.
// 16 clusters x 8 CTAs; cluster cid owns batches 4cid..4cid+3.
// CTA rank r owns j in [32r, 32r+32) (local col = jl*4 + g).
// Warp w: cols 8w..8w+7, all 4 batches. Lane: k-slice {lane+32u}.
// h pushed via st.async.shared::cluster.mbarrier::complete_tx (the store
// carries the completion to the TARGET CTA's mbarrier); consumers wait on
// their LOCAL mbarrier for 4096 tx bytes. No barrier.cluster in the loop.
// Backpressure: passing the wait for buf A implies every peer finished
// reading buf B (reads precede stores in program order), so writing buf B
// next step is race-free.
// SMEM: ws[256][132] @0, hb[2][256][4] @33792, mbar[2] static.
// ============================================================
#define SM_HB (HH * WST)
#define SMEM_FLOATS (SM_HB + 2 * HH * 4)
#define SMEM_BYTES  (SMEM_FLOATS * 4)
#define TXB 4096u   /* bytes per h-buffer fill: 1024 floats */

__global__ void __launch_bounds__(NTHR, 1) __cluster_dims__(CLUS, 1, 1)
lstm_kernel(const float* __restrict__ Wh, const float* __restrict__ bias,
            float* __restrict__ out)
{
    extern __shared__ float sm[];
    __shared__ __align__(8) ull mbar[2];
    float* ws = sm;
    float* hb = sm + SM_HB;

    const int tid  = threadIdx.x;
    const int w    = tid >> 5;
    const int lane = tid & 31;
    unsigned rank;
    asm("mov.u32 %0, %%cluster_ctarank;" : "=r"(rank));
    const int cid = blockIdx.x >> 3;

    // one-time: W_h slice ws[k*132 + jl*4 + g] = Wh[g][k][32r + jl]
    for (int idx = tid; idx < HH * 128; idx += NTHR) {
        int k = idx >> 7, rem = idx & 127;
        int g = rem >> 5, jl = rem & 31;
        ws[k * WST + jl * 4 + g] =
            __ldg(Wh + ((size_t)g * HH + k) * HH + (rank << 5) + jl);
    }

    const unsigned mb_u = smem_u32(mbar);
    if (tid == 0) {
        asm volatile("mbarrier.init.shared.b64 [%0], 1;" :: "r"(mb_u) : "memory");
        asm volatile("mbarrier.init.shared.b64 [%0], 1;" :: "r"(mb_u + 8) : "memory");
    }
    __syncthreads();
    CLUSTER_ARRIVE(); CLUSTER_WAIT();   // mbarrier inits visible before any st.async
    if (tid == 0) {                     // first-use expect_tx for both phases
        asm volatile("mbarrier.arrive.expect_tx.shared.b64 _, [%0], %1;"
                     :: "r"(mb_u), "r"(TXB) : "memory");
        asm volatile("mbarrier.arrive.expect_tx.shared.b64 _, [%0], %1;"
                     :: "r"(mb_u + 8), "r"(TXB) : "memory");
    }

    const int  col  = (w << 3) + (lane & 7);
    const int  b_l  = lane >> 3;
    const int  j    = (int)(rank << 5) + (col >> 2);
    const int  gg_  = col & 3;
    const int  bse  = lane & 28;
    const bool upd  = (lane & 3) == 0;
    const float biasv = __ldg(bias + (size_t)gg_ * HH + j);
    const int  myb  = (cid << 2) + b_l;
    const float* gxp = g_gx + (((size_t)myb * HH + j) << 2) + gg_;

    // hoisted: remote hb bases; remote mbar = rb[r] + mbdelta (+8 for buf 1)
    const unsigned hb_u = smem_u32(hb);
    unsigned rb[CLUS];
    #pragma unroll
    for (int r = 0; r < CLUS; ++r) rb[r] = mapa_rank(hb_u, (unsigned)r);
    const unsigned mbdelta = mb_u - hb_u;
    const unsigned joff = (unsigned)j * 16 + ((unsigned)b_l << 2);

    float creg = 0.f;

    for (int t = 0; t < TT; ++t) {
        float gxv = __ldg(gxp + (size_t)t * (BB * HH * 4));  // issued before wait

        ull acc2[16];
        #pragma unroll
        for (int i = 0; i < 16; ++i) acc2[i] = 0ull;

        if (t > 0) {
            // ---- consumer wait on LOCAL mbar[t&1] (acquire, cluster scope) ----
            {
                const unsigned mb = mb_u + ((unsigned)(t & 1) << 3);
                const unsigned par = ((unsigned)(t - 1) >> 1) & 1u;
                asm volatile(
                    "{\n\t.reg .pred p;\n\t"
                    "WAIT_%=:\n\t"
                    "mbarrier.try_wait.parity.acquire.cluster.shared::cta.b64 p, [%0], %1, 0x989680;\n\t"
                    "@p bra.uni DONE_%=;\n\t"
                    "bra.uni WAIT_%=;\n\t"
                    "DONE_%=:\n\t}"
                    :: "r"(mb), "r"(par) : "memory");
                if (tid == 0)   // re-arm this mbar for its use at step t+2
                    asm volatile("mbarrier.arrive.expect_tx.shared.b64 _, [%0], %1;"
                                 :: "r"(mb), "r"(TXB) : "memory");
            }
            const float* hbr = hb + ((t & 1) << 10);
            const float* wsw = ws + (w << 3);
            #pragma unroll
            for (int u = 0; u < 8; ++u) {
                const int k = lane + (u << 5);
                float4 hv = *(const float4*)(hbr + (k << 2));
                ulonglong2 w0 = *(const ulonglong2*)(wsw + k * WST);
                ulonglong2 w1 = *(const ulonglong2*)(wsw + k * WST + 4);
                ull h0 = pk2(hv.x), h1 = pk2(hv.y), h2 = pk2(hv.z), h3 = pk2(hv.w);
                fma2(acc2[0],  h0, w0.x); fma2(acc2[1],  h0, w0.y);
                fma2(acc2[2],  h0, w1.x); fma2(acc2[3],  h0, w1.y);
                fma2(acc2[4],  h1, w0.x); fma2(acc2[5],  h1, w0.y);
                fma2(acc2[6],  h1, w1.x); fma2(acc2[7],  h1, w1.y);
                fma2(acc2[8],  h2, w0.x); fma2(acc2[9],  h2, w0.y);
                fma2(acc2[10], h2, w1.x); fma2(acc2[11], h2, w1.y);
                fma2(acc2[12], h3, w0.x); fma2(acc2[13], h3, w0.y);
                fma2(acc2[14], h3, w1.x); fma2(acc2[15], h3, w1.y);
            }
        }

        // packed butterfly reduce-scatter: lane l <- output (b=l>>3, col=8w+(l&7))
        #pragma unroll
        for (int n = 16; n >= 2; n >>= 1) {
            const int m = n >> 1;
            #pragma unroll
            for (int s = 0; s < m; ++s) {
                ull lo = acc2[s], hi = acc2[s + m];
                ull send = (lane & n) ? lo : hi;
                ull keep = (lane & n) ? hi : lo;
                acc2[s] = add2(keep, __shfl_xor_sync(0xffffffffu, send, n));
            }
        }
        float pre;
        {
            unsigned u0, u1;
            asm("mov.b64 {%0, %1}, %2;" : "=r"(u0), "=r"(u1) : "l"(acc2[0]));
            float a0 = __uint_as_float(u0), a1 = __uint_as_float(u1);
            float send = (lane & 1) ? a0 : a1;
            float keep = (lane & 1) ? a1 : a0;
            pre = keep + __shfl_xor_sync(0xffffffffu, send, 1);
        }
        pre += gxv + biasv;

        // gather 4 gates (cols jl*4+0..3 live at lanes bse..bse+3)
        float pf = __shfl_sync(0xffffffffu, pre, bse | 1);
        float pg = __shfl_sync(0xffffffffu, pre, bse | 2);
        float po = __shfl_sync(0xffffffffu, pre, bse | 3);
        float hv_out = 0.f;
        if (upd) {
            float ig = sig_ap(pre);
            float fg = sig_ap(pf);
            float gv = tanh_ap(pg);
            float og = sig_ap(po);
            creg = fg * creg + ig * gv;
            hv_out = og * tanh_ap(creg);
            if (t + 1 < TT) {
                // push h_t to all 8 CTAs; each store signals the TARGET's mbar
                const unsigned boff = (unsigned)((t & 1) ^ 1);
                const unsigned off  = (boff << 12) + joff;
                const unsigned moff = mbdelta + (boff << 3);
                const unsigned hbits = __float_as_uint(hv_out);
                #pragma unroll
                for (int r = 0; r < CLUS; ++r) {
                    asm volatile(
                        "st.async.shared::cluster.mbarrier::complete_tx::bytes.b32 [%0], %1, [%2];"
                        :: "r"(rb[r] + off), "r"(hbits), "r"(rb[r] + moff)
                        : "memory");
                }
            }
        }

        if (upd)            // off the inter-CTA critical path
            out[((size_t)myb * TT + t) * HH + j] = hv_out;
    }

    CLUSTER_ARRIVE(); CLUSTER_WAIT();   // no early exit while peers may store into us
}

// ============================================================
extern "C" void kernel_launch(void* const* d_in, const int* in_sizes, int n_in,
                              void* d_out, int out_size)
{
    const float* x  = (const float*)d_in[0];   // [B, T, I]
    const float* Wx = (const float*)d_in[1];   // [4, I, H]
    const float* Wh = (const float*)d_in[2];   // [4, H, H]
    const float* b  = (const float*)d_in[3];   // [4, H]
    float* out = (float*)d_out;                // [B, T, H]

    cudaFuncSetAttribute(gx_kernel,
                         cudaFuncAttributeMaxDynamicSharedMemorySize, GX_SMEM_BYTES);
    cudaFuncSetAttribute(lstm_kernel,
                         cudaFuncAttributeMaxDynamicSharedMemorySize, SMEM_BYTES);

    gx_kernel<<<dim3(TT, 8), 512, GX_SMEM_BYTES>>>(x, Wx);
    lstm_kernel<<<NBLK, NTHR, SMEM_BYTES>>>(Wh, b, out);
}

// round 13
// speedup vs baseline: 1.4324x; 1.0224x over previous
#include <cuda_runtime.h>
#include <math.h>

typedef unsigned long long ull;

#define TT 2048
#define BB 64
#define II 128
#define HH 256
#define NBLK 128            /* 16 clusters x 8 CTAs */
#define CLUS 8
#define NTHR 512
#define HXS  68             /* gx-kernel x staging row stride */
#define WST  132            /* W_h slice row stride (128 cols + 4 pad) */

// ---- device scratch (static) ----
__device__ __align__(16) float g_gx[(size_t)TT * BB * HH * 4];   // [t][b][j][g]

// ---- helpers ----
__device__ __forceinline__ ull pk2(float v) {
    ull r; unsigned u = __float_as_uint(v);
    asm("mov.b64 %0, {%1, %1};" : "=l"(r) : "r"(u));
    return r;
}
__device__ __forceinline__ void fma2(ull& d, ull a, ull b) {
    asm("fma.rn.f32x2 %0, %1, %2, %0;" : "+l"(d) : "l"(a), "l"(b));
}
__device__ __forceinline__ ull add2(ull a, ull b) {
    ull r; asm("add.rn.f32x2 %0, %1, %2;" : "=l"(r) : "l"(a), "l"(b));
    return r;
}
__device__ __forceinline__ float tanh_ap(float x) {
    float y; asm("tanh.approx.f32 %0, %1;" : "=f"(y) : "f"(x));
    return y;
}
__device__ __forceinline__ float sig_ap(float x) {
    return fmaf(0.5f, tanh_ap(0.5f * x), 0.5f);
}
__device__ __forceinline__ unsigned smem_u32(const void* p) {
    unsigned a;
    asm("{ .reg .u64 t; cvta.to.shared.u64 t, %1; cvt.u32.u64 %0, t; }"
        : "=r"(a) : "l"(p));
    return a;
}
__device__ __forceinline__ unsigned mapa_rank(unsigned laddr, unsigned rank) {
    unsigned r;
    asm("mapa.shared::cluster.u32 %0, %1, %2;" : "=r"(r) : "r"(laddr), "r"(rank));
    return r;
}
__device__ __forceinline__ void mbar_wait(unsigned mb, unsigned par) {
    asm volatile(
        "{\n\t.reg .pred p;\n\t"
        "WAIT_%=:\n\t"
        "mbarrier.try_wait.parity.acquire.cluster.shared::cta.b64 p, [%0], %1, 0x989680;\n\t"
        "@p bra.uni DONE_%=;\n\t"
        "bra.uni WAIT_%=;\n\t"
        "DONE_%=:\n\t}"
        :: "r"(mb), "r"(par) : "memory");
}
#define CLUSTER_ARRIVE() asm volatile("barrier.cluster.arrive.aligned;" ::: "memory")
#define CLUSTER_WAIT()   asm volatile("barrier.cluster.wait.aligned;" ::: "memory")

// ============================================================
// Kernel 1: precompute gx[t][b][j][g] = (x_t . W_x), transpose fused.
// grid (t=2048, cb=8): cb covers h-cols 32cb..32cb+31 (x 4 gates).
// ============================================================
#define GX_XS 0
#define GX_WS (II * HXS)
#define GX_SMEM_FLOATS (GX_WS + II * 128)
#define GX_SMEM_BYTES  (GX_SMEM_FLOATS * 4)

__global__ void __launch_bounds__(512) gx_kernel(const float* __restrict__ x,
                                                 const float* __restrict__ Wx)
{
    extern __shared__ float sm[];
    float* xs  = sm + GX_XS;    // xs[i*68 + b]
    float* ws2 = sm + GX_WS;    // ws2[k*128 + hl*4 + g]

    const int t    = blockIdx.x;
    const int cb   = blockIdx.y;
    const int tid  = threadIdx.x;
    const int lane = tid & 31;
    const int bq   = tid >> 5;

    #pragma unroll
    for (int jj = 0; jj < 16; ++jj) {
        int idx = tid + jj * 512;
        int b = idx >> 7, i = idx & 127;
        xs[i * HXS + b] = __ldg(x + ((size_t)b * TT + t) * II + i);
    }
    #pragma unroll
    for (int jj = 0; jj < 32; ++jj) {
        int idx = tid + jj * 512;
        int k = idx >> 7, rem = idx & 127;
        int g = rem >> 5, hl = rem & 31;
        ws2[k * 128 + hl * 4 + g] = __ldg(Wx + ((size_t)g * II + k) * HH + (cb << 5) + hl);
    }
    __syncthreads();

    ull acc2[8];
    #pragma unroll
    for (int i = 0; i < 8; ++i) acc2[i] = 0ull;

    const float* xp = xs + (bq << 2);
    const float* wp = ws2 + (lane << 2);
    #pragma unroll 4
    for (int k = 0; k < II; ++k) {
        float4 hv = *(const float4*)(xp + k * HXS);
        ulonglong2 wv = *(const ulonglong2*)(wp + k * 128);
        ull h0 = pk2(hv.x), h1 = pk2(hv.y), h2 = pk2(hv.z), h3 = pk2(hv.w);
        fma2(acc2[0], h0, wv.x); fma2(acc2[1], h0, wv.y);
        fma2(acc2[2], h1, wv.x); fma2(acc2[3], h1, wv.y);
        fma2(acc2[4], h2, wv.x); fma2(acc2[5], h2, wv.y);
        fma2(acc2[6], h3, wv.x); fma2(acc2[7], h3, wv.y);
    }

    #pragma unroll
    for (int r = 0; r < 4; ++r) {
        int b = (bq << 2) + r;
        ulonglong2 v; v.x = acc2[r * 2]; v.y = acc2[r * 2 + 1];
        *(ulonglong2*)(g_gx + (((size_t)t * BB + b) * HH + (cb << 5) + lane) * 4) = v;
    }
}

// ============================================================
// Kernel 2: clustered LSTM, st.async h-exchange split into 2 half-group
// mbarriers (ranks 0-3 / 4-7). u-iter u of the FMA loop consumes exactly
// rank u's h chunk, so the consumer computes on half A while half B is
// still in flight. Per-lane gate activation before the gather shortens
// the upd-lane critical path to 1 MUFU + 1 tanh(c).
// SMEM: ws[256][132] @0, hb[2][256][4] @33792, mbar[2][2] static.
// ============================================================
#define SM_HB (HH * WST)
#define SMEM_FLOATS (SM_HB + 2 * HH * 4)
#define SMEM_BYTES  (SMEM_FLOATS * 4)
#define TXH 2048u   /* bytes per half-group: ranks r..r+3 = 512 floats */

__global__ void __launch_bounds__(NTHR, 1) __cluster_dims__(CLUS, 1, 1)
lstm_kernel(const float* __restrict__ Wh, const float* __restrict__ bias,
            float* __restrict__ out)
{
    extern __shared__ float sm[];
    __shared__ __align__(8) ull mbar[4];   // [buf][halfgroup]
    float* ws = sm;
    float* hb = sm + SM_HB;

    const int tid  = threadIdx.x;
    const int w    = tid >> 5;
    const int lane = tid & 31;
    unsigned rank;
    asm("mov.u32 %0, %%cluster_ctarank;" : "=r"(rank));
    const int cid = blockIdx.x >> 3;

    // one-time: W_h slice ws[k*132 + jl*4 + g] = Wh[g][k][32r + jl]
    for (int idx = tid; idx < HH * 128; idx += NTHR) {
        int k = idx >> 7, rem = idx & 127;
        int g = rem >> 5, jl = rem & 31;
        ws[k * WST + jl * 4 + g] =
            __ldg(Wh + ((size_t)g * HH + k) * HH + (rank << 5) + jl);
    }

    const unsigned mb_u = smem_u32(mbar);
    if (tid == 0) {
        #pragma unroll
        for (int i = 0; i < 4; ++i)
            asm volatile("mbarrier.init.shared.b64 [%0], 1;"
                         :: "r"(mb_u + (i << 3)) : "memory");
    }
    __syncthreads();
    CLUSTER_ARRIVE(); CLUSTER_WAIT();   // mbarrier inits visible before any st.async
    if (tid == 0) {                     // first-use expect_tx for all 4 mbars
        #pragma unroll
        for (int i = 0; i < 4; ++i)
            asm volatile("mbarrier.arrive.expect_tx.shared.b64 _, [%0], %1;"
                         :: "r"(mb_u + (i << 3)), "r"(TXH) : "memory");
    }

    const int  col  = (w << 3) + (lane & 7);
    const int  b_l  = lane >> 3;
    const int  j    = (int)(rank << 5) + (col >> 2);
    const int  gg_  = col & 3;
    const int  bse  = lane & 28;
    const bool upd  = (lane & 3) == 0;
    const float biasv = __ldg(bias + (size_t)gg_ * HH + j);
    const int  myb  = (cid << 2) + b_l;
    const float* gxp = g_gx + (((size_t)myb * HH + j) << 2) + gg_;

    // hoisted: remote hb bases; this CTA's half-group = rank>>2
    const unsigned hb_u = smem_u32(hb);
    unsigned rb[CLUS];
    #pragma unroll
    for (int r = 0; r < CLUS; ++r) rb[r] = mapa_rank(hb_u, (unsigned)r);
    const unsigned mbdelta = mb_u - hb_u + ((rank >> 2) << 3);  // +grp slot
    const unsigned joff = (unsigned)j * 16 + ((unsigned)b_l << 2);

    float creg = 0.f;

    for (int t = 0; t < TT; ++t) {
        float gxv = __ldg(gxp + (size_t)t * (BB * HH * 4));  // issued before wait

        ull acc2[16];
        #pragma unroll
        for (int i = 0; i < 16; ++i) acc2[i] = 0ull;

        if (t > 0) {
            const unsigned par = ((unsigned)(t - 1) >> 1) & 1u;
            const unsigned mbb = mb_u + ((unsigned)(t & 1) << 4);
            const float* hbr = hb + ((t & 1) << 10);
            const float* wsw = ws + (w << 3);

            // ---- half A: ranks 0-3 (k < 128) ----
            mbar_wait(mbb, par);
            if (tid == 0)
                asm volatile("mbarrier.arrive.expect_tx.shared.b64 _, [%0], %1;"
                             :: "r"(mbb), "r"(TXH) : "memory");
            #pragma unroll
            for (int u = 0; u < 4; ++u) {
                const int k = lane + (u << 5);
                float4 hv = *(const float4*)(hbr + (k << 2));
                ulonglong2 w0 = *(const ulonglong2*)(wsw + k * WST);
                ulonglong2 w1 = *(const ulonglong2*)(wsw + k * WST + 4);
                ull h0 = pk2(hv.x), h1 = pk2(hv.y), h2 = pk2(hv.z), h3 = pk2(hv.w);
                fma2(acc2[0],  h0, w0.x); fma2(acc2[1],  h0, w0.y);
                fma2(acc2[2],  h0, w1.x); fma2(acc2[3],  h0, w1.y);
                fma2(acc2[4],  h1, w0.x); fma2(acc2[5],  h1, w0.y);
                fma2(acc2[6],  h1, w1.x); fma2(acc2[7],  h1, w1.y);
                fma2(acc2[8],  h2, w0.x); fma2(acc2[9],  h2, w0.y);
                fma2(acc2[10], h2, w1.x); fma2(acc2[11], h2, w1.y);
                fma2(acc2[12], h3, w0.x); fma2(acc2[13], h3, w0.y);
                fma2(acc2[14], h3, w1.x); fma2(acc2[15], h3, w1.y);
            }
            // ---- half B: ranks 4-7 (k >= 128) ----
            mbar_wait(mbb + 8, par);
            if (tid == 0)
                asm volatile("mbarrier.arrive.expect_tx.shared.b64 _, [%0], %1;"
                             :: "r"(mbb + 8), "r"(TXH) : "memory");
            #pragma unroll
            for (int u = 4; u < 8; ++u) {
                const int k = lane + (u << 5);
                float4 hv = *(const float4*)(hbr + (k << 2));
                ulonglong2 w0 = *(const ulonglong2*)(wsw + k * WST);
                ulonglong2 w1 = *(const ulonglong2*)(wsw + k * WST + 4);
                ull h0 = pk2(hv.x), h1 = pk2(hv.y), h2 = pk2(hv.z), h3 = pk2(hv.w);
                fma2(acc2[0],  h0, w0.x); fma2(acc2[1],  h0, w0.y);
                fma2(acc2[2],  h0, w1.x); fma2(acc2[3],  h0, w1.y);
                fma2(acc2[4],  h1, w0.x); fma2(acc2[5],  h1, w0.y);
                fma2(acc2[6],  h1, w1.x); fma2(acc2[7],  h1, w1.y);
                fma2(acc2[8],  h2, w0.x); fma2(acc2[9],  h2, w0.y);
                fma2(acc2[10], h2, w1.x); fma2(acc2[11], h2, w1.y);
                fma2(acc2[12], h3, w0.x); fma2(acc2[13], h3, w0.y);
                fma2(acc2[14], h3, w1.x); fma2(acc2[15], h3, w1.y);
            }
        }

        // packed butterfly reduce-scatter: lane l <- output (b=l>>3, col=8w+(l&7))
        #pragma unroll
        for (int n = 16; n >= 2; n >>= 1) {
            const int m = n >> 1;
            #pragma unroll
            for (int s = 0; s < m; ++s) {
                ull lo = acc2[s], hi = acc2[s + m];
                ull send = (lane & n) ? lo : hi;
                ull keep = (lane & n) ? hi : lo;
                acc2[s] = add2(keep, __shfl_xor_sync(0xffffffffu, send, n));
            }
        }
        float pre;
        {
            unsigned u0, u1;
            asm("mov.b64 {%0, %1}, %2;" : "=r"(u0), "=r"(u1) : "l"(acc2[0]));
            float a0 = __uint_as_float(u0), a1 = __uint_as_float(u1);
            float send = (lane & 1) ? a0 : a1;
            float keep = (lane & 1) ? a1 : a0;
            pre = keep + __shfl_xor_sync(0xffffffffu, send, 1);
        }
        pre += gxv + biasv;

        // per-lane activation (gate gg_: 2 -> tanh, else sigmoid), THEN gather
        float av = (gg_ == 2) ? tanh_ap(pre) : sig_ap(pre);
        float fg = __shfl_sync(0xffffffffu, av, bse | 1);
        float gv = __shfl_sync(0xffffffffu, av, bse | 2);
        float og = __shfl_sync(0xffffffffu, av, bse | 3);
        float hv_out = 0.f;
        if (upd) {
            creg = fg * creg + av * gv;           // av = i-gate on upd lanes
            hv_out = og * tanh_ap(creg);
            if (t + 1 < TT) {
                // push h_t to all 8 CTAs; each store signals the TARGET's
                // mbar[buf][my halfgroup]
                const unsigned boff = (unsigned)((t & 1) ^ 1);
                const unsigned off  = (boff << 12) + joff;
                const unsigned moff = mbdelta + (boff << 4);
                const unsigned hbits = __float_as_uint(hv_out);
                #pragma unroll
                for (int r = 0; r < CLUS; ++r) {
                    asm volatile(
                        "st.async.shared::cluster.mbarrier::complete_tx::bytes.b32 [%0], %1, [%2];"
                        :: "r"(rb[r] + off), "r"(hbits), "r"(rb[r] + moff)
                        : "memory");
                }
            }
        }

        if (upd)            // off the inter-CTA critical path
            out[((size_t)myb * TT + t) * HH + j] = hv_out;
    }

    CLUSTER_ARRIVE(); CLUSTER_WAIT();   // no early exit while peers may store into us
}

// ============================================================
extern "C" void kernel_launch(void* const* d_in, const int* in_sizes, int n_in,
                              void* d_out, int out_size)
{
    const float* x  = (const float*)d_in[0];   // [B, T, I]
    const float* Wx = (const float*)d_in[1];   // [4, I, H]
    const float* Wh = (const float*)d_in[2];   // [4, H, H]
    const float* b  = (const float*)d_in[3];   // [4, H]
    float* out = (float*)d_out;                // [B, T, H]

    cudaFuncSetAttribute(gx_kernel,
                         cudaFuncAttributeMaxDynamicSharedMemorySize, GX_SMEM_BYTES);
    cudaFuncSetAttribute(lstm_kernel,
                         cudaFuncAttributeMaxDynamicSharedMemorySize, SMEM_BYTES);

    gx_kernel<<<dim3(TT, 8), 512, GX_SMEM_BYTES>>>(x, Wx);
    lstm_kernel<<<NBLK, NTHR, SMEM_BYTES>>>(Wh, b, out);
}